// round 13
// baseline (speedup 1.0000x reference)
#include <cuda_runtime.h>
#include <cuda_fp16.h>
#include <cstdint>

#define BR   3
#define H    1024
#define E    3
#define T    8192
#define CAP  2731
#define NW   (9 * 1024 * 1024)
#define NF   (8 * 3 * 1024 * 1024)
#define WSCALE 64.0f
#define INVWSCALE 0.015625f

// ---------------- device scratch ----------------
__device__ int    g_idx [BR * T];
__device__ float  g_gate[BR * T];
__device__ int    g_perm[BR * E * CAP];
__device__ int    g_m   [BR * E];
__device__ int    g_dropE[BR * E * T];
__device__ __half g_f16[NF];
__device__ __half g_w16[NW];

__device__ __forceinline__ uint32_t smem_u32(const void* p) {
    uint32_t a;
    asm("{ .reg .u64 t; cvta.to.shared.u64 t, %1; cvt.u32.u64 %0, t; }" : "=r"(a) : "l"(p));
    return a;
}

// ---------------- 1) merged prep (R12) ----------------
__global__ void prep_kernel(const float* __restrict__ feat,
                            const float* __restrict__ gw,
                            const float* __restrict__ ew) {
    __shared__ __align__(16) float s_w[3072];
    int bx = blockIdx.x;
    int tid = threadIdx.x;
    if (bx < 1536) {
        int br  = bx / 512;
        int grp = bx % 512;
        const float* w = gw + br * (H * E);
        #pragma unroll
        for (int q = 0; q < 3; q++)
            ((float4*)s_w)[q * 256 + tid] = ((const float4*)w)[q * 256 + tid];
        __syncthreads();

        int warp = tid >> 5, lane = tid & 31;
        int tb = grp * 16 + warp * 2;
        int off[2];
        #pragma unroll
        for (int tk = 0; tk < 2; tk++) {
            int t = tb + tk;
            int b = t >> 10, s = t & 1023;
            off[tk] = ((b * 3 + br) * 1024 + s) << 10;
        }
        float a0[2] = {0.f, 0.f}, a1[2] = {0.f, 0.f}, a2[2] = {0.f, 0.f};

        #pragma unroll
        for (int c = 0; c < 4; c++) {
            int h0 = c * 256 + lane * 8;
            float wv[24];
            const float4* wr4 = (const float4*)(s_w + h0 * 3);
            #pragma unroll
            for (int q = 0; q < 6; q++) *(float4*)&wv[q * 4] = wr4[q];
            #pragma unroll
            for (int tk = 0; tk < 2; tk++) {
                const float* x = feat + off[tk];
                float4 v0 = *(const float4*)(x + h0);
                float4 v1 = *(const float4*)(x + h0 + 4);
                float f[8] = {v0.x, v0.y, v0.z, v0.w, v1.x, v1.y, v1.z, v1.w};
                __half hh[8];
                #pragma unroll
                for (int j = 0; j < 8; j++) hh[j] = __float2half_rn(f[j]);
                *(uint4*)(g_f16 + off[tk] + h0) = *(uint4*)hh;
                #pragma unroll
                for (int j = 0; j < 8; j++) {
                    a0[tk] = fmaf(f[j], wv[j * 3 + 0], a0[tk]);
                    a1[tk] = fmaf(f[j], wv[j * 3 + 1], a1[tk]);
                    a2[tk] = fmaf(f[j], wv[j * 3 + 2], a2[tk]);
                }
            }
        }
        #pragma unroll
        for (int tk = 0; tk < 2; tk++) {
            float s0 = a0[tk], s1 = a1[tk], s2 = a2[tk];
            #pragma unroll
            for (int d = 16; d; d >>= 1) {
                s0 += __shfl_xor_sync(0xffffffffu, s0, d);
                s1 += __shfl_xor_sync(0xffffffffu, s1, d);
                s2 += __shfl_xor_sync(0xffffffffu, s2, d);
            }
            if (lane == 0) {
                int t = tb + tk;
                int e = 0; float m = s0;
                if (s1 > m) { m = s1; e = 1; }
                if (s2 > m) { m = s2; e = 2; }
                float sum = expf(s0 - m) + expf(s1 - m) + expf(s2 - m);
                g_idx [br * T + t] = e;
                g_gate[br * T + t] = 1.0f / sum;
            }
        }
    } else {
        int i = (bx - 1536) * 2048 + tid * 8;
        float4 v0 = *(const float4*)(ew + i);
        float4 v1 = *(const float4*)(ew + i + 4);
        __half h[8] = {__float2half_rn(v0.x * WSCALE), __float2half_rn(v0.y * WSCALE),
                       __float2half_rn(v0.z * WSCALE), __float2half_rn(v0.w * WSCALE),
                       __float2half_rn(v1.x * WSCALE), __float2half_rn(v1.y * WSCALE),
                       __float2half_rn(v1.z * WSCALE), __float2half_rn(v1.w * WSCALE)};
        *(uint4*)(g_w16 + i) = *(uint4*)h;
    }
}

// ---------------- 2) scan + perm + atomic-free drop zeroing (R12) ----------------
__global__ void scan_kernel(float* __restrict__ out) {
    int br   = blockIdx.x;
    int tid  = threadIdx.x;
    int lane = tid & 31, warp = tid >> 5;
    int t0   = tid * 8;

    __shared__ int s_nde[E];

    int idxs[8];
    *(int4*)&idxs[0] = *(const int4*)(g_idx + br * T + t0);
    *(int4*)&idxs[4] = *(const int4*)(g_idx + br * T + t0 + 4);
    unsigned long long c = 0;
    #pragma unroll
    for (int i = 0; i < 8; i++) c += 1ULL << (21 * idxs[i]);

    unsigned long long v = c;
    #pragma unroll
    for (int d = 1; d < 32; d <<= 1) {
        unsigned long long n = __shfl_up_sync(0xffffffffu, v, d);
        if (lane >= d) v += n;
    }
    __shared__ unsigned long long wsum[32];
    if (lane == 31) wsum[warp] = v;
    __syncthreads();
    if (warp == 0) {
        unsigned long long w = wsum[lane];
        #pragma unroll
        for (int d = 1; d < 32; d <<= 1) {
            unsigned long long n = __shfl_up_sync(0xffffffffu, w, d);
            if (lane >= d) w += n;
        }
        wsum[lane] = w;
    }
    __syncthreads();

    unsigned long long run = v - c + (warp ? wsum[warp - 1] : 0ULL);
    #pragma unroll
    for (int i = 0; i < 8; i++) {
        int e   = idxs[i];
        int pos = (int)((run >> (21 * e)) & 0x1FFFFFULL);
        run += 1ULL << (21 * e);
        if (pos < CAP) {
            g_perm[(br * E + e) * CAP + pos] = t0 + i;
        } else {
            g_dropE[(br * E + e) * T + (pos - CAP)] = t0 + i;
        }
    }
    if (tid == 1023) {
        #pragma unroll
        for (int e = 0; e < E; e++) {
            int tot = (int)((run >> (21 * e)) & 0x1FFFFFULL);
            g_m[br * E + e] = tot < CAP ? tot : CAP;
            s_nde[e] = tot > CAP ? tot - CAP : 0;
        }
    }
    __syncthreads();

    #pragma unroll
    for (int e = 0; e < E; e++) {
        int nd = s_nde[e];
        for (int i = warp; i < nd; i += 32) {
            int t = g_dropE[(br * E + e) * T + i];
            int b = t >> 10, s = t & 1023;
            float4* p = (float4*)(out + ((size_t)((b * 3 + br) * 1024 + s) << 10));
            #pragma unroll
            for (int q = 0; q < 8; q++)
                p[lane + q * 32] = make_float4(0.f, 0.f, 0.f, 0.f);
        }
    }
}

// ---------------- 4) fp16-accumulate mma GEMM, K=32 fp32 regroup ----------------
#define BK       32
#define NKITER   (H / BK)        // 32
#define STAGES   4
#define ROWB     80
#define TILE_B   (128 * ROWB)
#define STG_B    (2 * TILE_B)

#define SM_AOFF  0
#define SM_TOK   512
#define SM_GATE  1024
#define SM_BIAS  1536
#define SM_TILES 2048
#define SMEM_DYN (SM_TILES + STAGES * STG_B)   // 83968

#define CP16(dst, src) \
    asm volatile("cp.async.cg.shared.global [%0], [%1], 16;" :: "r"(dst), "l"(src))
#define CP_COMMIT() asm volatile("cp.async.commit_group;" ::: "memory")

__device__ __forceinline__ void ldmA(uint32_t* r, uint32_t addr) {
    asm volatile("ldmatrix.sync.aligned.m8n8.x4.shared.b16 {%0,%1,%2,%3}, [%4];"
                 : "=r"(r[0]), "=r"(r[1]), "=r"(r[2]), "=r"(r[3]) : "r"(addr));
}
// D = A*B + C, all-fp16 C/D (2 regs), separate C input
__device__ __forceinline__ void mma_f16_dc(uint32_t* d, const uint32_t* a, const uint32_t* b,
                                           uint32_t c0, uint32_t c1) {
    asm volatile(
        "mma.sync.aligned.m16n8k16.row.col.f16.f16.f16.f16 "
        "{%0,%1}, {%2,%3,%4,%5}, {%6,%7}, {%8,%9};"
        : "=r"(d[0]), "=r"(d[1])
        : "r"(a[0]), "r"(a[1]), "r"(a[2]), "r"(a[3]), "r"(b[0]), "r"(b[1]),
          "r"(c0), "r"(c1));
}
__device__ __forceinline__ void mma_f16_acc(uint32_t* c, const uint32_t* a, const uint32_t* b) {
    asm volatile(
        "mma.sync.aligned.m16n8k16.row.col.f16.f16.f16.f16 "
        "{%0,%1}, {%2,%3,%4,%5}, {%6,%7}, {%0,%1};"
        : "+r"(c[0]), "+r"(c[1])
        : "r"(a[0]), "r"(a[1]), "r"(a[2]), "r"(a[3]), "r"(b[0]), "r"(b[1]));
}

__global__ void __launch_bounds__(256, 2)
moe_gemm_mma(const float* __restrict__ eb, float* __restrict__ out) {
    extern __shared__ char smem[];
    int z  = blockIdx.z;
    int br = z / 3;
    int m  = g_m[z];
    int n0 = blockIdx.x * 128;
    int m0 = blockIdx.y * 128;
    if (m0 >= m) return;

    uint32_t sbase = smem_u32(smem);
    int tid  = threadIdx.x;
    int wid  = tid >> 5, lane = tid & 31;
    int wm   = wid & 1, wn = wid >> 1;

    int*   s_aoff = (int*)(smem + SM_AOFF);
    int*   s_tok  = (int*)(smem + SM_TOK);
    float* s_gate = (float*)(smem + SM_GATE);
    float* s_bias = (float*)(smem + SM_BIAS);

    if (tid < 128) {
        int r = m0 + tid;
        int tok = -1, off = 0;
        float gv = 0.f;
        if (r < m) {
            tok = g_perm[z * CAP + r];
            int b = tok >> 10, s = tok & 1023;
            off = ((b * 3 + br) * 1024 + s) << 10;
            gv  = g_gate[br * T + tok];
        }
        s_aoff[tid] = off;
        s_tok [tid] = tok;
        s_gate[tid] = gv;
    } else {
        s_bias[tid - 128] = eb[z * H + n0 + (tid - 128)];
    }
    __syncthreads();

    int r0 = tid >> 2, ch = tid & 3;
    int r1 = r0 + 64;
    const __half* gA0 = g_f16 + s_aoff[r0] + ch * 8;
    const __half* gA1 = g_f16 + s_aoff[r1] + ch * 8;
    size_t wbase = (size_t)z * H * H + ch * 8;
    const __half* gB0 = g_w16 + wbase + (size_t)(n0 + r0) * H;
    const __half* gB1 = g_w16 + wbase + (size_t)(n0 + r1) * H;

    auto issue = [&](int stg, int it) {
        uint32_t d = sbase + SM_TILES + stg * STG_B + (uint32_t)(r0 * ROWB + ch * 16);
        int k0 = it * BK;
        CP16(d,                      gA0 + k0);
        CP16(d + 64 * ROWB,          gA1 + k0);
        CP16(d + TILE_B,             gB0 + k0);
        CP16(d + TILE_B + 64 * ROWB, gB1 + k0);
        CP_COMMIT();
    };
    issue(0, 0);
    issue(1, 1);
    issue(2, 2);

    uint32_t a_lm = (uint32_t)((wm * 64 + (lane & 15)) * ROWB + (lane >> 4) * 16);
    uint32_t b_lm = (uint32_t)((wn * 32 + (lane & 7) + ((lane >> 4) & 1) * 8) * ROWB
                               + ((lane >> 3) & 1) * 16);
    uint32_t tiles = sbase + SM_TILES;

    float acc[4][4][4];
    #pragma unroll
    for (int i = 0; i < 4; i++)
        #pragma unroll
        for (int j = 0; j < 4; j++)
            #pragma unroll
            for (int k = 0; k < 4; k++) acc[i][j][k] = 0.f;

    for (int it = 0; it < NKITER; it++) {
        if (it < NKITER - 2)       asm volatile("cp.async.wait_group 2;" ::: "memory");
        else if (it == NKITER - 2) asm volatile("cp.async.wait_group 1;" ::: "memory");
        else                       asm volatile("cp.async.wait_group 0;" ::: "memory");
        __syncthreads();

        uint32_t sb = tiles + (it & (STAGES - 1)) * STG_B;
        // load fragments for BOTH k-steps up front
        uint32_t af[2][4][4], bh[2][4][2];
        #pragma unroll
        for (int kk = 0; kk < 2; kk++) {
            uint32_t kb = kk * 32;
            #pragma unroll
            for (int mt = 0; mt < 4; mt++)
                ldmA(af[kk][mt], sb + a_lm + kb + mt * 16 * ROWB);
            #pragma unroll
            for (int p = 0; p < 2; p++) {
                uint32_t rh[4];
                ldmA(rh, sb + TILE_B + b_lm + kb + p * 16 * ROWB);
                bh[kk][p * 2][0]     = rh[0]; bh[kk][p * 2][1]     = rh[1];
                bh[kk][p * 2 + 1][0] = rh[2]; bh[kk][p * 2 + 1][1] = rh[3];
            }
        }
        if (it + 3 < NKITER) issue((it + 3) & (STAGES - 1), it + 3);

        // per tile: 2 fp16-acc mmas (K=32 group), then fp32 re-accumulate
        #pragma unroll
        for (int mt = 0; mt < 4; mt++)
            #pragma unroll
            for (int nt = 0; nt < 4; nt++) {
                uint32_t cfrag[2];
                mma_f16_dc(cfrag, af[0][mt], bh[0][nt], 0u, 0u);
                mma_f16_acc(cfrag, af[1][mt], bh[1][nt]);
                float2 lo = __half22float2(*reinterpret_cast<__half2*>(&cfrag[0]));
                float2 hi = __half22float2(*reinterpret_cast<__half2*>(&cfrag[1]));
                acc[mt][nt][0] += lo.x;
                acc[mt][nt][1] += lo.y;
                acc[mt][nt][2] += hi.x;
                acc[mt][nt][3] += hi.y;
            }
    }

    // epilogue: out = gate * (acc/64 + bias)
    int g = lane >> 2, tig = lane & 3;
    #pragma unroll
    for (int mt = 0; mt < 4; mt++) {
        int ra = wm * 64 + mt * 16 + g;
        int rb = ra + 8;
        int tok0 = s_tok[ra], tok1 = s_tok[rb];
        float gv0 = s_gate[ra], gv1 = s_gate[rb];
        float* o0 = out + (size_t)s_aoff[ra] + n0;
        float* o1 = out + (size_t)s_aoff[rb] + n0;
        #pragma unroll
        for (int nt = 0; nt < 4; nt++) {
            int col = wn * 32 + nt * 8 + tig * 2;
            float b0 = s_bias[col], b1 = s_bias[col + 1];
            if (tok0 >= 0) {
                float2 v = {gv0 * (acc[mt][nt][0] * INVWSCALE + b0),
                            gv0 * (acc[mt][nt][1] * INVWSCALE + b1)};
                *(float2*)(o0 + col) = v;
            }
            if (tok1 >= 0) {
                float2 v = {gv1 * (acc[mt][nt][2] * INVWSCALE + b0),
                            gv1 * (acc[mt][nt][3] * INVWSCALE + b1)};
                *(float2*)(o1 + col) = v;
            }
        }
    }
}

// ---------------- launch ----------------
extern "C" void kernel_launch(void* const* d_in, const int* in_sizes, int n_in,
                              void* d_out, int out_size) {
    const float* feat = (const float*)d_in[0];
    const float* gw   = (const float*)d_in[1];
    const float* ew   = (const float*)d_in[2];
    const float* eb   = (const float*)d_in[3];
    float* out = (float*)d_out;

    cudaFuncSetAttribute(moe_gemm_mma, cudaFuncAttributeMaxDynamicSharedMemorySize, SMEM_DYN);

    prep_kernel<<<1536 + NW / 2048, 256>>>(feat, gw, ew);
    scan_kernel<<<BR, 1024>>>(out);
    moe_gemm_mma<<<dim3(H / 128, (CAP + 127) / 128, BR * E), 256, SMEM_DYN>>>(eb, out);
}

// round 14
// speedup vs baseline: 1.9015x; 1.9015x over previous
#include <cuda_runtime.h>
#include <cuda_fp16.h>
#include <cstdint>

#define BR   3
#define H    1024
#define E    3
#define T    8192
#define CAP  2731
#define NW   (9 * 1024 * 1024)
#define NF   (8 * 3 * 1024 * 1024)
#define WSCALE 64.0f
#define INVWSCALE 0.015625f

// ---------------- device scratch ----------------
__device__ int    g_idx [BR * T];
__device__ float  g_gate[BR * T];
__device__ int    g_perm[BR * E * CAP];
__device__ int    g_m   [BR * E];
__device__ int    g_dropE[BR * E * T];
__device__ __half g_f16[NF];
__device__ __half g_w16[NW];

__device__ __forceinline__ uint32_t smem_u32(const void* p) {
    uint32_t a;
    asm("{ .reg .u64 t; cvta.to.shared.u64 t, %1; cvt.u32.u64 %0, t; }" : "=r"(a) : "l"(p));
    return a;
}

// ---------------- 1) feat+gate prep (R12 structure, feat-only) ----------------
// 1536 blocks: warp = 2 tokens (16/block), gate weights staged in smem.
__global__ void prep_kernel(const float* __restrict__ feat,
                            const float* __restrict__ gw) {
    __shared__ __align__(16) float s_w[3072];
    int bx = blockIdx.x;
    int tid = threadIdx.x;
    int br  = bx / 512;
    int grp = bx % 512;
    const float* w = gw + br * (H * E);
    #pragma unroll
    for (int q = 0; q < 3; q++)
        ((float4*)s_w)[q * 256 + tid] = ((const float4*)w)[q * 256 + tid];
    __syncthreads();

    int warp = tid >> 5, lane = tid & 31;
    int tb = grp * 16 + warp * 2;
    int off[2];
    #pragma unroll
    for (int tk = 0; tk < 2; tk++) {
        int t = tb + tk;
        int b = t >> 10, s = t & 1023;
        off[tk] = ((b * 3 + br) * 1024 + s) << 10;
    }
    float a0[2] = {0.f, 0.f}, a1[2] = {0.f, 0.f}, a2[2] = {0.f, 0.f};

    #pragma unroll
    for (int c = 0; c < 4; c++) {
        int h0 = c * 256 + lane * 8;
        float wv[24];
        const float4* wr4 = (const float4*)(s_w + h0 * 3);
        #pragma unroll
        for (int q = 0; q < 6; q++) *(float4*)&wv[q * 4] = wr4[q];
        #pragma unroll
        for (int tk = 0; tk < 2; tk++) {
            const float* x = feat + off[tk];
            float4 v0 = *(const float4*)(x + h0);
            float4 v1 = *(const float4*)(x + h0 + 4);
            float f[8] = {v0.x, v0.y, v0.z, v0.w, v1.x, v1.y, v1.z, v1.w};
            __half hh[8];
            #pragma unroll
            for (int j = 0; j < 8; j++) hh[j] = __float2half_rn(f[j]);
            *(uint4*)(g_f16 + off[tk] + h0) = *(uint4*)hh;
            #pragma unroll
            for (int j = 0; j < 8; j++) {
                a0[tk] = fmaf(f[j], wv[j * 3 + 0], a0[tk]);
                a1[tk] = fmaf(f[j], wv[j * 3 + 1], a1[tk]);
                a2[tk] = fmaf(f[j], wv[j * 3 + 2], a2[tk]);
            }
        }
    }
    #pragma unroll
    for (int tk = 0; tk < 2; tk++) {
        float s0 = a0[tk], s1 = a1[tk], s2 = a2[tk];
        #pragma unroll
        for (int d = 16; d; d >>= 1) {
            s0 += __shfl_xor_sync(0xffffffffu, s0, d);
            s1 += __shfl_xor_sync(0xffffffffu, s1, d);
            s2 += __shfl_xor_sync(0xffffffffu, s2, d);
        }
        if (lane == 0) {
            int t = tb + tk;
            int e = 0; float m = s0;
            if (s1 > m) { m = s1; e = 1; }
            if (s2 > m) { m = s2; e = 2; }
            float sum = expf(s0 - m) + expf(s1 - m) + expf(s2 - m);
            g_idx [br * T + t] = e;
            g_gate[br * T + t] = 1.0f / sum;
        }
    }
}

// ---------------- 2) scan (blocks 0-2) + weight-convert (blocks 3+) ----------------
// 1024 threads. Conv blocks: 8192 elems each -> NW/8192 = 1152 blocks.
__global__ void scan_conv_kernel(const float* __restrict__ ew, float* __restrict__ out) {
    if (blockIdx.x >= BR) {
        // weight convert: fp16(64*W), 8 elems/thread
        int i = (blockIdx.x - BR) * 8192 + threadIdx.x * 8;
        float4 v0 = *(const float4*)(ew + i);
        float4 v1 = *(const float4*)(ew + i + 4);
        __half h[8] = {__float2half_rn(v0.x * WSCALE), __float2half_rn(v0.y * WSCALE),
                       __float2half_rn(v0.z * WSCALE), __float2half_rn(v0.w * WSCALE),
                       __float2half_rn(v1.x * WSCALE), __float2half_rn(v1.y * WSCALE),
                       __float2half_rn(v1.z * WSCALE), __float2half_rn(v1.w * WSCALE)};
        *(uint4*)(g_w16 + i) = *(uint4*)h;
        return;
    }

    int br   = blockIdx.x;
    int tid  = threadIdx.x;
    int lane = tid & 31, warp = tid >> 5;
    int t0   = tid * 8;

    __shared__ int s_nde[E];

    int idxs[8];
    *(int4*)&idxs[0] = *(const int4*)(g_idx + br * T + t0);
    *(int4*)&idxs[4] = *(const int4*)(g_idx + br * T + t0 + 4);
    unsigned long long c = 0;
    #pragma unroll
    for (int i = 0; i < 8; i++) c += 1ULL << (21 * idxs[i]);

    unsigned long long v = c;
    #pragma unroll
    for (int d = 1; d < 32; d <<= 1) {
        unsigned long long n = __shfl_up_sync(0xffffffffu, v, d);
        if (lane >= d) v += n;
    }
    __shared__ unsigned long long wsum[32];
    if (lane == 31) wsum[warp] = v;
    __syncthreads();
    if (warp == 0) {
        unsigned long long w = wsum[lane];
        #pragma unroll
        for (int d = 1; d < 32; d <<= 1) {
            unsigned long long n = __shfl_up_sync(0xffffffffu, w, d);
            if (lane >= d) w += n;
        }
        wsum[lane] = w;
    }
    __syncthreads();

    unsigned long long run = v - c + (warp ? wsum[warp - 1] : 0ULL);
    #pragma unroll
    for (int i = 0; i < 8; i++) {
        int e   = idxs[i];
        int pos = (int)((run >> (21 * e)) & 0x1FFFFFULL);
        run += 1ULL << (21 * e);
        if (pos < CAP) {
            g_perm[(br * E + e) * CAP + pos] = t0 + i;
        } else {
            g_dropE[(br * E + e) * T + (pos - CAP)] = t0 + i;
        }
    }
    if (tid == 1023) {
        #pragma unroll
        for (int e = 0; e < E; e++) {
            int tot = (int)((run >> (21 * e)) & 0x1FFFFFULL);
            g_m[br * E + e] = tot < CAP ? tot : CAP;
            s_nde[e] = tot > CAP ? tot - CAP : 0;
        }
    }
    __syncthreads();

    #pragma unroll
    for (int e = 0; e < E; e++) {
        int nd = s_nde[e];
        for (int i = warp; i < nd; i += 32) {
            int t = g_dropE[(br * E + e) * T + i];
            int b = t >> 10, s = t & 1023;
            float4* p = (float4*)(out + ((size_t)((b * 3 + br) * 1024 + s) << 10));
            #pragma unroll
            for (int q = 0; q < 8; q++)
                p[lane + q * 32] = make_float4(0.f, 0.f, 0.f, 0.f);
        }
    }
}

// ---------------- 4) 1-pass fp16 mma.sync gathered GEMM (R12 config, FROZEN) ----------------
#define BK       32
#define NKITER   (H / BK)        // 32
#define STAGES   4
#define ROWB     80
#define TILE_B   (128 * ROWB)
#define STG_B    (2 * TILE_B)

#define SM_AOFF  0
#define SM_TOK   512
#define SM_GATE  1024
#define SM_BIAS  1536
#define SM_TILES 2048
#define SMEM_DYN (SM_TILES + STAGES * STG_B)   // 83968

#define CP16(dst, src) \
    asm volatile("cp.async.cg.shared.global [%0], [%1], 16;" :: "r"(dst), "l"(src))
#define CP_COMMIT() asm volatile("cp.async.commit_group;" ::: "memory")

__device__ __forceinline__ void ldmA(uint32_t* r, uint32_t addr) {
    asm volatile("ldmatrix.sync.aligned.m8n8.x4.shared.b16 {%0,%1,%2,%3}, [%4];"
                 : "=r"(r[0]), "=r"(r[1]), "=r"(r[2]), "=r"(r[3]) : "r"(addr));
}
__device__ __forceinline__ void mma16816(float* c, const uint32_t* a, const uint32_t* b) {
    asm volatile(
        "mma.sync.aligned.m16n8k16.row.col.f32.f16.f16.f32 "
        "{%0,%1,%2,%3}, {%4,%5,%6,%7}, {%8,%9}, {%0,%1,%2,%3};"
        : "+f"(c[0]), "+f"(c[1]), "+f"(c[2]), "+f"(c[3])
        : "r"(a[0]), "r"(a[1]), "r"(a[2]), "r"(a[3]), "r"(b[0]), "r"(b[1]));
}

__global__ void __launch_bounds__(256, 2)
moe_gemm_mma(const float* __restrict__ eb, float* __restrict__ out) {
    extern __shared__ char smem[];
    int z  = blockIdx.z;
    int br = z / 3;
    int m  = g_m[z];
    int n0 = blockIdx.x * 128;
    int m0 = blockIdx.y * 128;
    if (m0 >= m) return;

    uint32_t sbase = smem_u32(smem);
    int tid  = threadIdx.x;
    int wid  = tid >> 5, lane = tid & 31;
    int wm   = wid & 1, wn = wid >> 1;

    int*   s_aoff = (int*)(smem + SM_AOFF);
    int*   s_tok  = (int*)(smem + SM_TOK);
    float* s_gate = (float*)(smem + SM_GATE);
    float* s_bias = (float*)(smem + SM_BIAS);

    if (tid < 128) {
        int r = m0 + tid;
        int tok = -1, off = 0;
        float gv = 0.f;
        if (r < m) {
            tok = g_perm[z * CAP + r];
            int b = tok >> 10, s = tok & 1023;
            off = ((b * 3 + br) * 1024 + s) << 10;
            gv  = g_gate[br * T + tok];
        }
        s_aoff[tid] = off;
        s_tok [tid] = tok;
        s_gate[tid] = gv;
    } else {
        s_bias[tid - 128] = eb[z * H + n0 + (tid - 128)];
    }
    __syncthreads();

    int r0 = tid >> 2, ch = tid & 3;
    int r1 = r0 + 64;
    const __half* gA0 = g_f16 + s_aoff[r0] + ch * 8;
    const __half* gA1 = g_f16 + s_aoff[r1] + ch * 8;
    size_t wbase = (size_t)z * H * H + ch * 8;
    const __half* gB0 = g_w16 + wbase + (size_t)(n0 + r0) * H;
    const __half* gB1 = g_w16 + wbase + (size_t)(n0 + r1) * H;

    auto issue = [&](int stg, int it) {
        uint32_t d = sbase + SM_TILES + stg * STG_B + (uint32_t)(r0 * ROWB + ch * 16);
        int k0 = it * BK;
        CP16(d,                      gA0 + k0);
        CP16(d + 64 * ROWB,          gA1 + k0);
        CP16(d + TILE_B,             gB0 + k0);
        CP16(d + TILE_B + 64 * ROWB, gB1 + k0);
        CP_COMMIT();
    };
    issue(0, 0);
    issue(1, 1);
    issue(2, 2);

    uint32_t a_lm = (uint32_t)((wm * 64 + (lane & 15)) * ROWB + (lane >> 4) * 16);
    uint32_t b_lm = (uint32_t)((wn * 32 + (lane & 7) + ((lane >> 4) & 1) * 8) * ROWB
                               + ((lane >> 3) & 1) * 16);
    uint32_t tiles = sbase + SM_TILES;

    float acc[4][4][4];
    #pragma unroll
    for (int i = 0; i < 4; i++)
        #pragma unroll
        for (int j = 0; j < 4; j++)
            #pragma unroll
            for (int k = 0; k < 4; k++) acc[i][j][k] = 0.f;

    for (int it = 0; it < NKITER; it++) {
        if (it < NKITER - 2)       asm volatile("cp.async.wait_group 2;" ::: "memory");
        else if (it == NKITER - 2) asm volatile("cp.async.wait_group 1;" ::: "memory");
        else                       asm volatile("cp.async.wait_group 0;" ::: "memory");
        __syncthreads();

        uint32_t sb = tiles + (it & (STAGES - 1)) * STG_B;
        #pragma unroll
        for (int kk = 0; kk < 2; kk++) {
            uint32_t kb = kk * 32;
            uint32_t af[4][4], bh[4][2];
            #pragma unroll
            for (int mt = 0; mt < 4; mt++)
                ldmA(af[mt], sb + a_lm + kb + mt * 16 * ROWB);
            #pragma unroll
            for (int p = 0; p < 2; p++) {
                uint32_t rh[4];
                ldmA(rh, sb + TILE_B + b_lm + kb + p * 16 * ROWB);
                bh[p * 2][0]     = rh[0]; bh[p * 2][1]     = rh[1];
                bh[p * 2 + 1][0] = rh[2]; bh[p * 2 + 1][1] = rh[3];
            }
            #pragma unroll
            for (int mt = 0; mt < 4; mt++)
                #pragma unroll
                for (int nt = 0; nt < 4; nt++)
                    mma16816(acc[mt][nt], af[mt], bh[nt]);

            if (kk == 0 && it + 3 < NKITER) issue((it + 3) & (STAGES - 1), it + 3);
        }
    }

    // epilogue: out = gate * (acc/64 + bias)
    int g = lane >> 2, tig = lane & 3;
    #pragma unroll
    for (int mt = 0; mt < 4; mt++) {
        int ra = wm * 64 + mt * 16 + g;
        int rb = ra + 8;
        int tok0 = s_tok[ra], tok1 = s_tok[rb];
        float gv0 = s_gate[ra], gv1 = s_gate[rb];
        float* o0 = out + (size_t)s_aoff[ra] + n0;
        float* o1 = out + (size_t)s_aoff[rb] + n0;
        #pragma unroll
        for (int nt = 0; nt < 4; nt++) {
            int col = wn * 32 + nt * 8 + tig * 2;
            float b0 = s_bias[col], b1 = s_bias[col + 1];
            if (tok0 >= 0) {
                float2 v = {gv0 * (acc[mt][nt][0] * INVWSCALE + b0),
                            gv0 * (acc[mt][nt][1] * INVWSCALE + b1)};
                *(float2*)(o0 + col) = v;
            }
            if (tok1 >= 0) {
                float2 v = {gv1 * (acc[mt][nt][2] * INVWSCALE + b0),
                            gv1 * (acc[mt][nt][3] * INVWSCALE + b1)};
                *(float2*)(o1 + col) = v;
            }
        }
    }
}

// ---------------- launch ----------------
extern "C" void kernel_launch(void* const* d_in, const int* in_sizes, int n_in,
                              void* d_out, int out_size) {
    const float* feat = (const float*)d_in[0];
    const float* gw   = (const float*)d_in[1];
    const float* ew   = (const float*)d_in[2];
    const float* eb   = (const float*)d_in[3];
    float* out = (float*)d_out;

    cudaFuncSetAttribute(moe_gemm_mma, cudaFuncAttributeMaxDynamicSharedMemorySize, SMEM_DYN);

    prep_kernel<<<1536, 256>>>(feat, gw);
    scan_conv_kernel<<<BR + NW / 8192, 1024>>>(ew, out);
    moe_gemm_mma<<<dim3(H / 128, (CAP + 127) / 128, BR * E), 256, SMEM_DYN>>>(eb, out);
}